// round 1
// baseline (speedup 1.0000x reference)
#include <cuda_runtime.h>
#include <math.h>

// Problem constants (fixed by reference setup_inputs)
#define BSZ   4096
#define D0    2048
#define D1    128
#define NTOT  8192            // 2*BSZ
#define TILE  64
#define BK    32
#define NTILES (NTOT / TILE)  // 128
// Flag threshold on l2 of feature 1. exp(-130/1.68) ~ 2.6e-34; dropped mass
// bounded by N^2 * 5 * 2.6e-34 ~ 9e-26 absolute vs answer ~2.4e-3. Provably safe.
#define L2_THRESH 130.0f

// ---- scratch (allocation-free rule: __device__ globals) ----
__device__ float  g_sq0[NTOT];
__device__ float  g_sq1[NTOT];
__device__ float  g_colsum[D0];
__device__ double g_sum_sq0;
__device__ double g_acc;
__device__ float  g_inv_bw[5];

// ---------------------------------------------------------------------------
// K0: zero the accumulators (must re-run every graph replay)
// ---------------------------------------------------------------------------
__global__ void k_init() {
    int i = blockIdx.x * blockDim.x + threadIdx.x;
    if (i < D0) g_colsum[i] = 0.0f;
    if (i == 0) { g_sum_sq0 = 0.0; g_acc = 0.0; }
}

// ---------------------------------------------------------------------------
// K1: per-row sum of squares for feature0 (2048) and feature1 (128)
// ---------------------------------------------------------------------------
__global__ __launch_bounds__(256) void k_rows(
    const float* __restrict__ src0, const float* __restrict__ tar0,
    const float* __restrict__ src1, const float* __restrict__ tar1)
{
    int n = blockIdx.x;
    int t = threadIdx.x;
    const float* r0 = (n < BSZ) ? (src0 + (size_t)n * D0) : (tar0 + (size_t)(n - BSZ) * D0);
    const float* r1 = (n < BSZ) ? (src1 + (size_t)n * D1) : (tar1 + (size_t)(n - BSZ) * D1);

    float s = 0.0f;
    const float4* p4 = (const float4*)r0;    // 512 float4
#pragma unroll
    for (int j = 0; j < 2; j++) {
        float4 v = p4[t + j * 256];
        s += v.x * v.x + v.y * v.y + v.z * v.z + v.w * v.w;
    }
    __shared__ float red[256];
    red[t] = s;
    __syncthreads();
    for (int off = 128; off > 0; off >>= 1) {
        if (t < off) red[t] += red[t + off];
        __syncthreads();
    }
    if (t == 0) {
        g_sq0[n] = red[0];
        atomicAdd(&g_sum_sq0, (double)red[0]);
    }
    __syncthreads();

    float s1 = 0.0f;
    if (t < D1) { float v = r1[t]; s1 = v * v; }
    red[t] = s1;
    __syncthreads();
    for (int off = 128; off > 0; off >>= 1) {
        if (t < off) red[t] += red[t + off];
        __syncthreads();
    }
    if (t == 0) g_sq1[n] = red[0];
}

// ---------------------------------------------------------------------------
// K2: column sums of feature0 (for analytic sum of l2 -> bandwidth)
// grid (8, 8): x = d-block of 256 columns, y = 1024-row chunk
// ---------------------------------------------------------------------------
__global__ __launch_bounds__(256) void k_col(
    const float* __restrict__ src0, const float* __restrict__ tar0)
{
    int d = blockIdx.x * 256 + threadIdx.x;
    int chunk = blockIdx.y;  // 0..7; chunks 0..3 -> src, 4..7 -> tar
    const float* base = (chunk < 4) ? (src0 + (size_t)chunk * 1024 * D0)
                                    : (tar0 + (size_t)(chunk - 4) * 1024 * D0);
    float s = 0.0f;
#pragma unroll 8
    for (int n = 0; n < 1024; n++) s += base[(size_t)n * D0 + d];
    atomicAdd(&g_colsum[d], s);
}

// ---------------------------------------------------------------------------
// K3: finalize bandwidth: sum_l2 = 2N*sum_sq0 - 2*||colsum||^2
// ---------------------------------------------------------------------------
__global__ __launch_bounds__(256) void k_bw() {
    int t = threadIdx.x;
    double s = 0.0;
    for (int d = t; d < D0; d += 256) {
        double c = (double)g_colsum[d];
        s += c * c;
    }
    __shared__ double red[256];
    red[t] = s;
    __syncthreads();
    for (int off = 128; off > 0; off >>= 1) {
        if (t < off) red[t] += red[t + off];
        __syncthreads();
    }
    if (t == 0) {
        double sum_l2 = 2.0 * (double)NTOT * g_sum_sq0 - 2.0 * red[0];
        double bw = sum_l2 / ((double)NTOT * (double)NTOT - (double)NTOT) / 4.0;
#pragma unroll
        for (int i = 0; i < 5; i++)
            g_inv_bw[i] = (float)(1.0 / (bw * (double)(1 << i)));
    }
}

// ---------------------------------------------------------------------------
// K4: fused classifier GEMM (feature1, fp32) + sparse exact epilogue.
// 64x64 tiles, 256 threads, 4x4 register blocking, K chunked by 32.
// Upper-triangle tiles only (weight 2 off-diag, 1 on diag).
// ---------------------------------------------------------------------------
__global__ __launch_bounds__(256) void k_tile(
    const float* __restrict__ src0, const float* __restrict__ tar0,
    const float* __restrict__ src1, const float* __restrict__ tar1)
{
    int bx = blockIdx.x;  // column tile
    int by = blockIdx.y;  // row tile
    if (bx < by) return;  // symmetry: only upper triangle

    __shared__ float As[TILE][BK + 1];
    __shared__ float Bs[TILE][BK + 1];

    int tid = threadIdx.x;
    int tx = tid & 15;
    int ty = tid >> 4;

    float acc[4][4] = {};
    int arow0 = by * TILE;
    int brow0 = bx * TILE;

    for (int k0 = 0; k0 < D1; k0 += BK) {
        __syncthreads();
        for (int idx = tid; idx < TILE * BK; idx += 256) {
            int r = idx >> 5;         // row within tile
            int k = idx & 31;         // k within chunk
            int an = arow0 + r;
            const float* pa = (an < BSZ) ? (src1 + (size_t)an * D1)
                                         : (tar1 + (size_t)(an - BSZ) * D1);
            As[r][k] = pa[k0 + k];
            int bn = brow0 + r;
            const float* pb = (bn < BSZ) ? (src1 + (size_t)bn * D1)
                                         : (tar1 + (size_t)(bn - BSZ) * D1);
            Bs[r][k] = pb[k0 + k];
        }
        __syncthreads();

#pragma unroll
        for (int k = 0; k < BK; k++) {
            float a[4], b[4];
#pragma unroll
            for (int i = 0; i < 4; i++) a[i] = As[ty * 4 + i][k];
#pragma unroll
            for (int j = 0; j < 4; j++) b[j] = Bs[tx * 4 + j][k];
#pragma unroll
            for (int i = 0; i < 4; i++)
#pragma unroll
                for (int j = 0; j < 4; j++)
                    acc[i][j] += a[i] * b[j];
        }
    }

    // Epilogue: threshold test; flagged pairs computed exactly.
    float sqa[4], sqb[4];
#pragma unroll
    for (int i = 0; i < 4; i++) sqa[i] = g_sq1[arow0 + ty * 4 + i];
#pragma unroll
    for (int j = 0; j < 4; j++) sqb[j] = g_sq1[brow0 + tx * 4 + j];

    float local = 0.0f;
#pragma unroll
    for (int i = 0; i < 4; i++) {
#pragma unroll
        for (int j = 0; j < 4; j++) {
            float l2 = sqa[i] + sqb[j] - 2.0f * acc[i][j];
            if (l2 < L2_THRESH) {
                int a = arow0 + ty * 4 + i;
                int b = brow0 + tx * 4 + j;
                float k1v = expf(-l2 * (1.0f / 1.68f));
                float l20;
                if (a == b) {
                    l20 = 0.0f;  // sq[a]+sq[a]-2*dot(a,a) == 0 by construction
                } else {
                    const float* ra = (a < BSZ) ? (src0 + (size_t)a * D0)
                                                : (tar0 + (size_t)(a - BSZ) * D0);
                    const float* rb = (b < BSZ) ? (src0 + (size_t)b * D0)
                                                : (tar0 + (size_t)(b - BSZ) * D0);
                    float dp = 0.0f;
                    for (int d = 0; d < D0; d += 4) {
                        float4 x = *(const float4*)(ra + d);
                        float4 y = *(const float4*)(rb + d);
                        dp += x.x * y.x + x.y * y.y + x.z * y.z + x.w * y.w;
                    }
                    l20 = g_sq0[a] + g_sq0[b] - 2.0f * dp;
                }
                float k0v = 0.0f;
#pragma unroll
                for (int q = 0; q < 5; q++) k0v += expf(-l20 * g_inv_bw[q]);
                local += k0v * k1v;
            }
        }
    }

    // block reduce + signed/weighted accumulate
    __shared__ float redf[256];
    redf[tid] = local;
    __syncthreads();
    for (int off = 128; off > 0; off >>= 1) {
        if (tid < off) redf[tid] += redf[tid + off];
        __syncthreads();
    }
    if (tid == 0 && redf[0] != 0.0f) {
        float w = (bx == by) ? 1.0f : 2.0f;
        float sgn = ((by < NTILES / 2) == (bx < NTILES / 2)) ? 1.0f : -1.0f;
        atomicAdd(&g_acc, (double)(redf[0] * w * sgn));
    }
}

// ---------------------------------------------------------------------------
// K5: write scalar output
// ---------------------------------------------------------------------------
__global__ void k_out(float* __restrict__ out) {
    out[0] = (float)(g_acc / ((double)BSZ * (double)BSZ));
}

extern "C" void kernel_launch(void* const* d_in, const int* in_sizes, int n_in,
                              void* d_out, int out_size)
{
    const float* src0 = (const float*)d_in[0];
    const float* src1 = (const float*)d_in[1];
    const float* tar0 = (const float*)d_in[2];
    const float* tar1 = (const float*)d_in[3];
    float* out = (float*)d_out;

    k_init<<<8, 256>>>();
    k_rows<<<NTOT, 256>>>(src0, tar0, src1, tar1);
    k_col<<<dim3(8, 8), 256>>>(src0, tar0);
    k_bw<<<1, 256>>>();
    k_tile<<<dim3(NTILES, NTILES), 256>>>(src0, tar0, src1, tar1);
    k_out<<<1, 1>>>(out);
}